// round 15
// baseline (speedup 1.0000x reference)
#include <cuda_runtime.h>
#include <math.h>

typedef unsigned long long ULL;

// ---------------- f32x2 packed-math helpers (sm_100+) --------------------
__device__ __forceinline__ ULL bcast2(float v) {
    ULL r; asm("mov.b64 %0, {%1, %1};" : "=l"(r) : "f"(v)); return r;
}
__device__ __forceinline__ void fma2(ULL& d, ULL a, ULL b) {
    asm("fma.rn.f32x2 %0, %1, %2, %0;" : "+l"(d) : "l"(a), "l"(b));
}
__device__ __forceinline__ float2 unpack2(ULL v) {
    float2 f; asm("mov.b64 {%0, %1}, %2;" : "=f"(f.x), "=f"(f.y) : "l"(v)); return f;
}
__device__ __forceinline__ float ex2(float x) {
    float r; asm("ex2.approx.f32 %0, %1;" : "=f"(r) : "f"(x)); return r;
}

// ---------------- scratch buffers (no allocation allowed) ----------------
__device__ float g_Q[4096 * 256];
__device__ float g_K[4096 * 256];     // reused post-attn as combined O
__device__ float g_V[4096 * 256];
__device__ float g_O[4096 * 256];     // attention numerator, kv-half 0
__device__ float g_Msg[4096 * 256];
__device__ float g_H[4096 * 512];     // first 4M floats: numerator, kv-half 1
__device__ float g_Den[2 * 16384];    // [z][b*4+h][2048]

// ---------------- GEMM core (f32x2) — R13 proven version ------------------
template <bool RELU>
__device__ __forceinline__ void gemm_body(
    const float* __restrict__ A0, const float* __restrict__ A1, int kSplit,
    const float* __restrict__ W, const float* __restrict__ pe, bool rotary,
    float* __restrict__ C, int N, int K,
    float (*As)[16], float (*Ws)[64])
{
    const int tid = threadIdx.x;
    const int tx = tid & 15;
    const int ty = tid >> 4;
    const int m0 = blockIdx.y * 128;
    const int n0 = blockIdx.x * 64;

    const int ar = tid >> 2;
    const int ak = (tid & 3) * 4;
    const int wk = tid >> 4;
    const int wc = (tid & 15) * 4;

    ULL acc2[8][2];
#pragma unroll
    for (int i = 0; i < 8; i++) { acc2[i][0] = 0ull; acc2[i][1] = 0ull; }

    const int nk = K >> 4;
    float4 pa0, pa1, pw;

    pa0 = *(const float4*)(A0 + (size_t)(m0 + ar) * kSplit + ak);
    pa1 = *(const float4*)(A0 + (size_t)(m0 + ar + 64) * kSplit + ak);
    pw  = *(const float4*)(W + (size_t)wk * N + n0 + wc);
    *(float4*)&As[ar][ak]      = pa0;
    *(float4*)&As[ar + 64][ak] = pa1;
    *(float4*)&Ws[wk][wc]      = pw;
    __syncthreads();

    for (int kt = 0; kt < nk; kt++) {
        if (kt + 1 < nk) {
            const int kb = (kt + 1) << 4;
            const float* src; int lda, kk;
            if (kb < kSplit) { src = A0; lda = kSplit;     kk = kb; }
            else             { src = A1; lda = K - kSplit; kk = kb - kSplit; }
            pa0 = *(const float4*)(src + (size_t)(m0 + ar) * lda + kk + ak);
            pa1 = *(const float4*)(src + (size_t)(m0 + ar + 64) * lda + kk + ak);
            pw  = *(const float4*)(W + (size_t)(kb + wk) * N + n0 + wc);
        }
#pragma unroll
        for (int k4 = 0; k4 < 4; k4++) {
            float4 av4[8];
#pragma unroll
            for (int i = 0; i < 8; i++)
                av4[i] = *(const float4*)&As[ty * 8 + i][k4 * 4];
#pragma unroll
            for (int kk = 0; kk < 4; kk++) {
                ulonglong2 w2 = *(const ulonglong2*)&Ws[k4 * 4 + kk][tx * 4];
#pragma unroll
                for (int i = 0; i < 8; i++) {
                    ULL a2 = bcast2(((const float*)&av4[i])[kk]);
                    fma2(acc2[i][0], a2, w2.x);
                    fma2(acc2[i][1], a2, w2.y);
                }
            }
        }
        __syncthreads();
        if (kt + 1 < nk) {
            *(float4*)&As[ar][ak]      = pa0;
            *(float4*)&As[ar + 64][ak] = pa1;
            *(float4*)&Ws[wk][wc]      = pw;
        }
        __syncthreads();
    }

#pragma unroll
    for (int i = 0; i < 8; i++) {
        const int m = m0 + ty * 8 + i;
        float2 u0 = unpack2(acc2[i][0]);
        float2 u1 = unpack2(acc2[i][1]);
        float v0 = u0.x, v1 = u0.y, v2 = u1.x, v3 = u1.y;
        if (RELU) {
            v0 = fmaxf(v0, 0.f); v1 = fmaxf(v1, 0.f);
            v2 = fmaxf(v2, 0.f); v3 = fmaxf(v3, 0.f);
        }
        if (rotary) {
            const int c0 = n0 + tx * 4;
            const float* pr = pe + ((size_t)m * 256 + c0) * 2;
            float4 p0 = *(const float4*)pr;
            float4 p1 = *(const float4*)(pr + 4);
            float e = v0, o = v1;
            v0 = e * p0.x - o * p0.y;
            v1 = o * p0.z + e * p0.w;
            e = v2; o = v3;
            v2 = e * p1.x - o * p1.y;
            v3 = o * p1.z + e * p1.w;
        }
        *(float4*)(C + (size_t)m * N + n0 + tx * 4) = make_float4(v0, v1, v2, v3);
    }
}

template <bool RELU, bool ROTARY>
__global__ __launch_bounds__(256) void gemm_k(
    const float* __restrict__ A0, const float* __restrict__ A1, int kSplit,
    const float* __restrict__ W, const float* __restrict__ pe,
    float* __restrict__ C, int M, int N, int K)
{
    __shared__ __align__(16) float As[128][16];
    __shared__ __align__(16) float Ws[16][64];
    gemm_body<RELU>(A0, A1, kSplit, W, pe, ROTARY, C, N, K, As, Ws);
}

// Fused Q/K/V projection: z selects {A, W, pe, C, rotary}. 384 CTAs.
__global__ __launch_bounds__(256) void qkv_k(
    const float* __restrict__ x, const float* __restrict__ src,
    const float* __restrict__ xpe, const float* __restrict__ spe,
    const float* __restrict__ Wq, const float* __restrict__ Wk,
    const float* __restrict__ Wv,
    float* __restrict__ Qb, float* __restrict__ Kb, float* __restrict__ Vb)
{
    __shared__ __align__(16) float As[128][16];
    __shared__ __align__(16) float Ws[16][64];
    const int z = blockIdx.z;
    const float* A  = (z == 0) ? x   : src;
    const float* W  = (z == 0) ? Wq  : (z == 1 ? Wk : Wv);
    const float* pe = (z == 0) ? xpe : spe;
    float* C        = (z == 0) ? Qb  : (z == 1 ? Kb : Vb);
    gemm_body<false>(A, nullptr, 256, W, pe, z < 2, C, 256, 256, As, Ws);
}

// ---------------- GEMM + fused LayerNorm (split columns, R13-proven) ------
__global__ __launch_bounds__(256) void gemm_ln_k(
    const float* __restrict__ A, const float* __restrict__ W, int K,
    const float* __restrict__ g, const float* __restrict__ b,
    const float* __restrict__ resid, float* __restrict__ out)
{
    __shared__ __align__(16) float As[32][16];
    __shared__ __align__(16) float Ws[16][256];

    const int tid = threadIdx.x;
    const int tx = tid & 31;
    const int ty = tid >> 5;
    const int m0 = blockIdx.x * 32;

    ULL acc2[4][4];
#pragma unroll
    for (int i = 0; i < 4; i++)
#pragma unroll
        for (int j = 0; j < 4; j++) acc2[i][j] = 0ull;

    const int nk = K >> 4;
    const int ar = tid >> 2, ak = (tid & 3) * 4;

    float4 pa, pw[4];
    if (tid < 128)
        pa = *(const float4*)(A + (size_t)(m0 + ar) * K + ak);
#pragma unroll
    for (int it = 0; it < 4; it++) {
        int gidx = tid + it * 256;
        int wr = gidx >> 6, wc = (gidx & 63) * 4;
        pw[it] = *(const float4*)(W + (size_t)wr * 256 + wc);
    }
    if (tid < 128) *(float4*)&As[ar][ak] = pa;
#pragma unroll
    for (int it = 0; it < 4; it++) {
        int gidx = tid + it * 256;
        int wr = gidx >> 6, wc = (gidx & 63) * 4;
        *(float4*)&Ws[wr][wc] = pw[it];
    }
    __syncthreads();

    for (int kt = 0; kt < nk; kt++) {
        if (kt + 1 < nk) {
            const int kb = (kt + 1) << 4;
            if (tid < 128)
                pa = *(const float4*)(A + (size_t)(m0 + ar) * K + kb + ak);
#pragma unroll
            for (int it = 0; it < 4; it++) {
                int gidx = tid + it * 256;
                int wr = gidx >> 6, wc = (gidx & 63) * 4;
                pw[it] = *(const float4*)(W + (size_t)(kb + wr) * 256 + wc);
            }
        }
#pragma unroll
        for (int k4 = 0; k4 < 4; k4++) {
            float4 av4[4];
#pragma unroll
            for (int i = 0; i < 4; i++)
                av4[i] = *(const float4*)&As[ty * 4 + i][k4 * 4];
#pragma unroll
            for (int kk = 0; kk < 4; kk++) {
                const float* wrow = &Ws[k4 * 4 + kk][0];
                ulonglong2 wA = *(const ulonglong2*)(wrow + tx * 4);
                ulonglong2 wB = *(const ulonglong2*)(wrow + 128 + tx * 4);
#pragma unroll
                for (int i = 0; i < 4; i++) {
                    ULL a2 = bcast2(((const float*)&av4[i])[kk]);
                    fma2(acc2[i][0], a2, wA.x);
                    fma2(acc2[i][1], a2, wA.y);
                    fma2(acc2[i][2], a2, wB.x);
                    fma2(acc2[i][3], a2, wB.y);
                }
            }
        }
        __syncthreads();
        if (kt + 1 < nk) {
            if (tid < 128) *(float4*)&As[ar][ak] = pa;
#pragma unroll
            for (int it = 0; it < 4; it++) {
                int gidx = tid + it * 256;
                int wr = gidx >> 6, wc = (gidx & 63) * 4;
                *(float4*)&Ws[wr][wc] = pw[it];
            }
        }
        __syncthreads();
    }

    const int c0 = tx * 4, c1 = 128 + tx * 4;
    const float4 gA = *(const float4*)(g + c0);
    const float4 gB = *(const float4*)(g + c1);
    const float4 bA = *(const float4*)(b + c0);
    const float4 bB = *(const float4*)(b + c1);

#pragma unroll
    for (int i = 0; i < 4; i++) {
        const int m = m0 + ty * 4 + i;
        float v[8];
        float2 u0 = unpack2(acc2[i][0]); v[0] = u0.x; v[1] = u0.y;
        float2 u1 = unpack2(acc2[i][1]); v[2] = u1.x; v[3] = u1.y;
        float2 u2 = unpack2(acc2[i][2]); v[4] = u2.x; v[5] = u2.y;
        float2 u3 = unpack2(acc2[i][3]); v[6] = u3.x; v[7] = u3.y;

        float s = 0.f, ss = 0.f;
#pragma unroll
        for (int j = 0; j < 8; j++) { s += v[j]; ss += v[j] * v[j]; }
#pragma unroll
        for (int off = 16; off; off >>= 1) {
            s  += __shfl_xor_sync(0xffffffffu, s, off);
            ss += __shfl_xor_sync(0xffffffffu, ss, off);
        }
        const float mu  = s * (1.f / 256.f);
        const float var = ss * (1.f / 256.f) - mu * mu;
        const float rs  = rsqrtf(var + 1e-5f);

        float r0 = (v[0] - mu) * rs * gA.x + bA.x;
        float r1 = (v[1] - mu) * rs * gA.y + bA.y;
        float r2 = (v[2] - mu) * rs * gA.z + bA.z;
        float r3 = (v[3] - mu) * rs * gA.w + bA.w;
        float r4 = (v[4] - mu) * rs * gB.x + bB.x;
        float r5 = (v[5] - mu) * rs * gB.y + bB.y;
        float r6 = (v[6] - mu) * rs * gB.z + bB.z;
        float r7 = (v[7] - mu) * rs * gB.w + bB.w;

        if (resid) {
            const float* rp = resid + (size_t)m * 256;
            float4 x0 = *(const float4*)(rp + c0);
            float4 x1 = *(const float4*)(rp + c1);
            r0 += x0.x; r1 += x0.y; r2 += x0.z; r3 += x0.w;
            r4 += x1.x; r5 += x1.y; r6 += x1.z; r7 += x1.w;
        }
        float* dst = out + (size_t)m * 256;
        *(float4*)(dst + c0) = make_float4(r0, r1, r2, r3);
        *(float4*)(dst + c1) = make_float4(r4, r5, r6, r7);
    }
}

// ---------------- FlashAttention (fp32, f32x2, split-KV, 2 CTAs/SM) -------
// 128 q/CTA, 64-key blocks, kv-half z = blockIdx.z (1024 keys each).
// smem 96 KB -> 2 CTAs/SM (4 warps/SMSP). No-max softmax => partial sums
// are exactly additive: CTA writes unnormalized numerator + denominator.
// QK: 4 rows x 8 split cols {tx*4, 32+tx*4}; PV: same row map -> den stays
// in registers. mov:fma2 = 1:4; all LDS phase-contiguous or broadcast.
__global__ __launch_bounds__(256, 2) void attn_k(
    const float* __restrict__ Q, const float* __restrict__ Kg,
    const float* __restrict__ Vg,
    float* __restrict__ N0, float* __restrict__ N1, float* __restrict__ Dp)
{
    extern __shared__ __align__(16) float sm[];
    float* Qs  = sm;                 // [128][64]  32 KB
    float* KsT = Qs + 128 * 64;      // [64][64]   (d, s) 16 KB
    float* Vs  = KsT + 64 * 64;      // [64][64]   16 KB
    float* Ps  = Vs + 64 * 64;       // [128][64]  32 KB

    const int tid = threadIdx.x;
    const int tx = tid & 7;      // col group: {tx*4, 32+tx*4}
    const int ty = tid >> 3;     // rows ty*4..+3  (0..31 -> 128 rows)
    const int q0 = blockIdx.x * 128;
    const int b = blockIdx.y >> 2;
    const int h = blockIdx.y & 3;
    const int z = blockIdx.z;

    const float* Qp = Q  + ((size_t)b * 2048 + q0) * 256 + h * 64;
    const float* Kp = Kg + ((size_t)b * 2048 + z * 1024) * 256 + h * 64;
    const float* Vp = Vg + ((size_t)b * 2048 + z * 1024) * 256 + h * 64;

    const float QSCALE = 0.18033688011112042f;  // 0.125 * log2(e)

    // ---- Q tile (scaled), stride 64 (broadcast reads; contiguous stores)
#pragma unroll
    for (int it = 0; it < 8; it++) {
        int g = tid + it * 256;
        int r = g >> 4, c = (g & 15) << 2;
        float4 q = *(const float4*)(Qp + (size_t)r * 256 + c);
        *(float4*)&Qs[r * 64 + c] =
            make_float4(q.x * QSCALE, q.y * QSCALE, q.z * QSCALE, q.w * QSCALE);
    }

    ULL o2[4][4];
    float den[4];
#pragma unroll
    for (int i = 0; i < 4; i++) {
        den[i] = 0.f;
#pragma unroll
        for (int j = 0; j < 4; j++) o2[i][j] = 0ull;
    }

    for (int kt = 0; kt < 16; kt++) {
        __syncthreads();   // prev PV done with KsT/Vs/Ps (and Qs stored)

        // ---- load K (transposed, [d][s]) + V ([s][d]) 64-key tiles
        const float* Kb = Kp + (size_t)kt * 64 * 256;
        const float* Vb = Vp + (size_t)kt * 64 * 256;
#pragma unroll
        for (int it = 0; it < 4; it++) {
            int g = tid + it * 256;        // 0..1023
            int s = g & 63, dg = g >> 6;   // dg 0..15
            float4 kv = *(const float4*)(Kb + (size_t)s * 256 + dg * 4);
            KsT[(dg * 4 + 0) * 64 + s] = kv.x;
            KsT[(dg * 4 + 1) * 64 + s] = kv.y;
            KsT[(dg * 4 + 2) * 64 + s] = kv.z;
            KsT[(dg * 4 + 3) * 64 + s] = kv.w;
            int sv = g >> 4, cv = (g & 15) << 2;
            *(float4*)&Vs[sv * 64 + cv] = *(const float4*)(Vb + (size_t)sv * 256 + cv);
        }
        __syncthreads();

        // ---- S = Q @ K^T : 4 rows x 8 split cols
        ULL s2[4][4];
#pragma unroll
        for (int i = 0; i < 4; i++)
#pragma unroll
            for (int j = 0; j < 4; j++) s2[i][j] = 0ull;

#pragma unroll
        for (int d4 = 0; d4 < 16; d4++) {
            float4 q4[4];
#pragma unroll
            for (int i = 0; i < 4; i++)
                q4[i] = *(const float4*)&Qs[(ty * 4 + i) * 64 + d4 * 4];
#pragma unroll
            for (int dd = 0; dd < 4; dd++) {
                const float* krow = &KsT[(d4 * 4 + dd) * 64];
                ulonglong2 kA = *(const ulonglong2*)(krow + tx * 4);
                ulonglong2 kB = *(const ulonglong2*)(krow + 32 + tx * 4);
#pragma unroll
                for (int i = 0; i < 4; i++) {
                    ULL qq = bcast2(((const float*)&q4[i])[dd]);
                    fma2(s2[i][0], qq, kA.x);
                    fma2(s2[i][1], qq, kA.y);
                    fma2(s2[i][2], qq, kB.x);
                    fma2(s2[i][3], qq, kB.y);
                }
            }
        }

        // ---- softmax without max-shift: p = 2^S, den += sum(p)
#pragma unroll
        for (int i = 0; i < 4; i++) {
            float p[8];
            float2 t0 = unpack2(s2[i][0]); p[0] = ex2(t0.x); p[1] = ex2(t0.y);
            float2 t1 = unpack2(s2[i][1]); p[2] = ex2(t1.x); p[3] = ex2(t1.y);
            float2 t2 = unpack2(s2[i][2]); p[4] = ex2(t2.x); p[5] = ex2(t2.y);
            float2 t3 = unpack2(s2[i][3]); p[6] = ex2(t3.x); p[7] = ex2(t3.y);
            den[i] += ((p[0] + p[1]) + (p[2] + p[3]))
                    + ((p[4] + p[5]) + (p[6] + p[7]));
            float* pr = &Ps[(ty * 4 + i) * 64];
            *(float4*)(pr + tx * 4)      = make_float4(p[0], p[1], p[2], p[3]);
            *(float4*)(pr + 32 + tx * 4) = make_float4(p[4], p[5], p[6], p[7]);
        }
        __syncthreads();   // Ps visible; all warps done with KsT

        // ---- O += P @ V : 4 rows x 8 split d-cols
#pragma unroll
        for (int k4 = 0; k4 < 16; k4++) {
            float4 p4[4];
#pragma unroll
            for (int i = 0; i < 4; i++)
                p4[i] = *(const float4*)&Ps[(ty * 4 + i) * 64 + k4 * 4];
#pragma unroll
            for (int kk = 0; kk < 4; kk++) {
                const float* vrow = &Vs[(k4 * 4 + kk) * 64];
                ulonglong2 vA = *(const ulonglong2*)(vrow + tx * 4);
                ulonglong2 vB = *(const ulonglong2*)(vrow + 32 + tx * 4);
#pragma unroll
                for (int i = 0; i < 4; i++) {
                    ULL pp = bcast2(((const float*)&p4[i])[kk]);
                    fma2(o2[i][0], pp, vA.x);
                    fma2(o2[i][1], pp, vA.y);
                    fma2(o2[i][2], pp, vB.x);
                    fma2(o2[i][3], pp, vB.y);
                }
            }
        }
    }

    // ---- reduce den across the 8-lane row group (xor 1,2,4)
#pragma unroll
    for (int i = 0; i < 4; i++) {
#pragma unroll
        for (int off = 4; off; off >>= 1)
            den[i] += __shfl_xor_sync(0xffffffffu, den[i], off);
    }

    // ---- write unnormalized numerator + denominator
    float* Np = (z == 0) ? N0 : N1;
    float* Op = Np + ((size_t)b * 2048 + q0) * 256 + h * 64;
#pragma unroll
    for (int i = 0; i < 4; i++) {
        const int row = ty * 4 + i;
        float2 a0 = unpack2(o2[i][0]);
        float2 a1 = unpack2(o2[i][1]);
        float2 a2 = unpack2(o2[i][2]);
        float2 a3 = unpack2(o2[i][3]);
        float* dst = Op + (size_t)row * 256;
        *(float4*)(dst + tx * 4)      = make_float4(a0.x, a0.y, a1.x, a1.y);
        *(float4*)(dst + 32 + tx * 4) = make_float4(a2.x, a2.y, a3.x, a3.y);
    }
    if (tx == 0) {
        float* dp = Dp + z * 16384 + ((size_t)(b * 4 + h)) * 2048 + q0;
#pragma unroll
        for (int i = 0; i < 4; i++) dp[ty * 4 + i] = den[i];
    }
}

// ---------------- combine: O = (N0 + N1) / (d0 + d1) ----------------------
__global__ __launch_bounds__(256) void comb_k(
    const float* __restrict__ N0, const float* __restrict__ N1,
    const float* __restrict__ Dp, float* __restrict__ Out)
{
    const int r = blockIdx.x;          // 0..4095
    const int c = threadIdx.x;         // 0..255
    const int bq = r & 2047, bb = r >> 11, hh = c >> 6;
    const int di = (bb * 4 + hh) * 2048 + bq;
    const float d = Dp[di] + Dp[16384 + di];
    const size_t idx = (size_t)r * 256 + c;
    Out[idx] = (N0[idx] + N1[idx]) / d;
}

// ---------------- launch -------------------------------------------------
extern "C" void kernel_launch(void* const* d_in, const int* in_sizes, int n_in,
                              void* d_out, int out_size)
{
    (void)in_sizes; (void)n_in; (void)out_size;
    const float* x   = (const float*)d_in[0];
    const float* src = (const float*)d_in[1];
    const float* xpe = (const float*)d_in[2];
    const float* spe = (const float*)d_in[3];
    const float* Wq  = (const float*)d_in[4];
    const float* Wk  = (const float*)d_in[5];
    const float* Wv  = (const float*)d_in[6];
    const float* Wm  = (const float*)d_in[7];
    const float* W1  = (const float*)d_in[8];
    const float* W2  = (const float*)d_in[9];
    const float* g1  = (const float*)d_in[10];
    const float* b1  = (const float*)d_in[11];
    const float* g2  = (const float*)d_in[12];
    const float* b2  = (const float*)d_in[13];
    float* out = (float*)d_out;

    float *Qb, *Kb, *Vb, *N0, *Msg, *Hb, *Dp;
    cudaGetSymbolAddress((void**)&Qb,  g_Q);
    cudaGetSymbolAddress((void**)&Kb,  g_K);
    cudaGetSymbolAddress((void**)&Vb,  g_V);
    cudaGetSymbolAddress((void**)&N0,  g_O);
    cudaGetSymbolAddress((void**)&Msg, g_Msg);
    cudaGetSymbolAddress((void**)&Hb,  g_H);
    cudaGetSymbolAddress((void**)&Dp,  g_Den);
    float* N1 = Hb;   // g_H free until W1

    const int ATTN_SMEM = (128 * 64 + 64 * 64 + 64 * 64 + 128 * 64) * 4; // 98304
    cudaFuncSetAttribute(attn_k, cudaFuncAttributeMaxDynamicSharedMemorySize, ATTN_SMEM);

    const dim3 blk(256);
    // fused Q/K/V projections (rotary on Q,K)
    qkv_k<<<dim3(4, 32, 3), blk>>>(x, src, xpe, spe, Wq, Wk, Wv, Qb, Kb, Vb);
    // attention: 256 CTAs (2 kv-halves), 2 CTAs/SM
    attn_k<<<dim3(16, 8, 2), blk, ATTN_SMEM>>>(Qb, Kb, Vb, N0, N1, Dp);
    // combine partials into g_K (K tiles are dead now)
    comb_k<<<4096, blk>>>(N0, N1, Dp, Kb);
    // message = LN(O @ Wm)   (fused)
    gemm_ln_k<<<128, blk>>>(Kb, Wm, 256, g1, b1, nullptr, Msg);
    // h = relu(concat(x, message) @ W1)
    gemm_k<true, false><<<dim3(8, 32), blk>>>(x, Msg, 256, W1, nullptr, Hb, 4096, 512, 512);
    // out = x + LN(h @ W2)   (fused)
    gemm_ln_k<<<128, blk>>>(Hb, W2, 512, g2, b2, x, out);
}

// round 16
// speedup vs baseline: 1.0411x; 1.0411x over previous
#include <cuda_runtime.h>
#include <math.h>

typedef unsigned long long ULL;

// ---------------- f32x2 packed-math helpers (sm_100+) --------------------
__device__ __forceinline__ ULL bcast2(float v) {
    ULL r; asm("mov.b64 %0, {%1, %1};" : "=l"(r) : "f"(v)); return r;
}
__device__ __forceinline__ void fma2(ULL& d, ULL a, ULL b) {
    asm("fma.rn.f32x2 %0, %1, %2, %0;" : "+l"(d) : "l"(a), "l"(b));
}
__device__ __forceinline__ float2 unpack2(ULL v) {
    float2 f; asm("mov.b64 {%0, %1}, %2;" : "=f"(f.x), "=f"(f.y) : "l"(v)); return f;
}
__device__ __forceinline__ float ex2(float x) {
    float r; asm("ex2.approx.f32 %0, %1;" : "=f"(r) : "f"(x)); return r;
}

// ---------------- scratch buffers (no allocation allowed) ----------------
__device__ float g_Q[4096 * 256];
__device__ float g_K[4096 * 256];
__device__ float g_V[4096 * 256];
__device__ float g_O[4096 * 256];
__device__ float g_Msg[4096 * 256];
__device__ float g_H[4096 * 512];

// ---------------- GEMM core (f32x2) — R13 proven version ------------------
template <bool RELU>
__device__ __forceinline__ void gemm_body(
    const float* __restrict__ A0, const float* __restrict__ A1, int kSplit,
    const float* __restrict__ W, const float* __restrict__ pe, bool rotary,
    float* __restrict__ C, int N, int K,
    float (*As)[16], float (*Ws)[64])
{
    const int tid = threadIdx.x;
    const int tx = tid & 15;
    const int ty = tid >> 4;
    const int m0 = blockIdx.y * 128;
    const int n0 = blockIdx.x * 64;

    const int ar = tid >> 2;
    const int ak = (tid & 3) * 4;
    const int wk = tid >> 4;
    const int wc = (tid & 15) * 4;

    ULL acc2[8][2];
#pragma unroll
    for (int i = 0; i < 8; i++) { acc2[i][0] = 0ull; acc2[i][1] = 0ull; }

    const int nk = K >> 4;
    float4 pa0, pa1, pw;

    pa0 = *(const float4*)(A0 + (size_t)(m0 + ar) * kSplit + ak);
    pa1 = *(const float4*)(A0 + (size_t)(m0 + ar + 64) * kSplit + ak);
    pw  = *(const float4*)(W + (size_t)wk * N + n0 + wc);
    *(float4*)&As[ar][ak]      = pa0;
    *(float4*)&As[ar + 64][ak] = pa1;
    *(float4*)&Ws[wk][wc]      = pw;
    __syncthreads();

    for (int kt = 0; kt < nk; kt++) {
        if (kt + 1 < nk) {
            const int kb = (kt + 1) << 4;
            const float* src; int lda, kk;
            if (kb < kSplit) { src = A0; lda = kSplit;     kk = kb; }
            else             { src = A1; lda = K - kSplit; kk = kb - kSplit; }
            pa0 = *(const float4*)(src + (size_t)(m0 + ar) * lda + kk + ak);
            pa1 = *(const float4*)(src + (size_t)(m0 + ar + 64) * lda + kk + ak);
            pw  = *(const float4*)(W + (size_t)(kb + wk) * N + n0 + wc);
        }
#pragma unroll
        for (int k4 = 0; k4 < 4; k4++) {
            float4 av4[8];
#pragma unroll
            for (int i = 0; i < 8; i++)
                av4[i] = *(const float4*)&As[ty * 8 + i][k4 * 4];
#pragma unroll
            for (int kk = 0; kk < 4; kk++) {
                ulonglong2 w2 = *(const ulonglong2*)&Ws[k4 * 4 + kk][tx * 4];
#pragma unroll
                for (int i = 0; i < 8; i++) {
                    ULL a2 = bcast2(((const float*)&av4[i])[kk]);
                    fma2(acc2[i][0], a2, w2.x);
                    fma2(acc2[i][1], a2, w2.y);
                }
            }
        }
        __syncthreads();
        if (kt + 1 < nk) {
            *(float4*)&As[ar][ak]      = pa0;
            *(float4*)&As[ar + 64][ak] = pa1;
            *(float4*)&Ws[wk][wc]      = pw;
        }
        __syncthreads();
    }

#pragma unroll
    for (int i = 0; i < 8; i++) {
        const int m = m0 + ty * 8 + i;
        float2 u0 = unpack2(acc2[i][0]);
        float2 u1 = unpack2(acc2[i][1]);
        float v0 = u0.x, v1 = u0.y, v2 = u1.x, v3 = u1.y;
        if (RELU) {
            v0 = fmaxf(v0, 0.f); v1 = fmaxf(v1, 0.f);
            v2 = fmaxf(v2, 0.f); v3 = fmaxf(v3, 0.f);
        }
        if (rotary) {
            const int c0 = n0 + tx * 4;
            const float* pr = pe + ((size_t)m * 256 + c0) * 2;
            float4 p0 = *(const float4*)pr;
            float4 p1 = *(const float4*)(pr + 4);
            float e = v0, o = v1;
            v0 = e * p0.x - o * p0.y;
            v1 = o * p0.z + e * p0.w;
            e = v2; o = v3;
            v2 = e * p1.x - o * p1.y;
            v3 = o * p1.z + e * p1.w;
        }
        *(float4*)(C + (size_t)m * N + n0 + tx * 4) = make_float4(v0, v1, v2, v3);
    }
}

template <bool RELU, bool ROTARY>
__global__ __launch_bounds__(256) void gemm_k(
    const float* __restrict__ A0, const float* __restrict__ A1, int kSplit,
    const float* __restrict__ W, const float* __restrict__ pe,
    float* __restrict__ C, int M, int N, int K)
{
    __shared__ __align__(16) float As[128][16];
    __shared__ __align__(16) float Ws[16][64];
    gemm_body<RELU>(A0, A1, kSplit, W, pe, ROTARY, C, N, K, As, Ws);
}

// Fused Q/K/V projection: z selects {A, W, pe, C, rotary}. 384 CTAs.
__global__ __launch_bounds__(256) void qkv_k(
    const float* __restrict__ x, const float* __restrict__ src,
    const float* __restrict__ xpe, const float* __restrict__ spe,
    const float* __restrict__ Wq, const float* __restrict__ Wk,
    const float* __restrict__ Wv,
    float* __restrict__ Qb, float* __restrict__ Kb, float* __restrict__ Vb)
{
    __shared__ __align__(16) float As[128][16];
    __shared__ __align__(16) float Ws[16][64];
    const int z = blockIdx.z;
    const float* A  = (z == 0) ? x   : src;
    const float* W  = (z == 0) ? Wq  : (z == 1 ? Wk : Wv);
    const float* pe = (z == 0) ? xpe : spe;
    float* C        = (z == 0) ? Qb  : (z == 1 ? Kb : Vb);
    gemm_body<false>(A, nullptr, 256, W, pe, z < 2, C, 256, 256, As, Ws);
}

// ---------------- GEMM + fused LayerNorm (split columns, R13-proven) ------
__global__ __launch_bounds__(256) void gemm_ln_k(
    const float* __restrict__ A, const float* __restrict__ W, int K,
    const float* __restrict__ g, const float* __restrict__ b,
    const float* __restrict__ resid, float* __restrict__ out)
{
    __shared__ __align__(16) float As[32][16];
    __shared__ __align__(16) float Ws[16][256];

    const int tid = threadIdx.x;
    const int tx = tid & 31;
    const int ty = tid >> 5;
    const int m0 = blockIdx.x * 32;

    ULL acc2[4][4];
#pragma unroll
    for (int i = 0; i < 4; i++)
#pragma unroll
        for (int j = 0; j < 4; j++) acc2[i][j] = 0ull;

    const int nk = K >> 4;
    const int ar = tid >> 2, ak = (tid & 3) * 4;

    float4 pa, pw[4];
    if (tid < 128)
        pa = *(const float4*)(A + (size_t)(m0 + ar) * K + ak);
#pragma unroll
    for (int it = 0; it < 4; it++) {
        int gidx = tid + it * 256;
        int wr = gidx >> 6, wc = (gidx & 63) * 4;
        pw[it] = *(const float4*)(W + (size_t)wr * 256 + wc);
    }
    if (tid < 128) *(float4*)&As[ar][ak] = pa;
#pragma unroll
    for (int it = 0; it < 4; it++) {
        int gidx = tid + it * 256;
        int wr = gidx >> 6, wc = (gidx & 63) * 4;
        *(float4*)&Ws[wr][wc] = pw[it];
    }
    __syncthreads();

    for (int kt = 0; kt < nk; kt++) {
        if (kt + 1 < nk) {
            const int kb = (kt + 1) << 4;
            if (tid < 128)
                pa = *(const float4*)(A + (size_t)(m0 + ar) * K + kb + ak);
#pragma unroll
            for (int it = 0; it < 4; it++) {
                int gidx = tid + it * 256;
                int wr = gidx >> 6, wc = (gidx & 63) * 4;
                pw[it] = *(const float4*)(W + (size_t)(kb + wr) * 256 + wc);
            }
        }
#pragma unroll
        for (int k4 = 0; k4 < 4; k4++) {
            float4 av4[4];
#pragma unroll
            for (int i = 0; i < 4; i++)
                av4[i] = *(const float4*)&As[ty * 4 + i][k4 * 4];
#pragma unroll
            for (int kk = 0; kk < 4; kk++) {
                const float* wrow = &Ws[k4 * 4 + kk][0];
                ulonglong2 wA = *(const ulonglong2*)(wrow + tx * 4);
                ulonglong2 wB = *(const ulonglong2*)(wrow + 128 + tx * 4);
#pragma unroll
                for (int i = 0; i < 4; i++) {
                    ULL a2 = bcast2(((const float*)&av4[i])[kk]);
                    fma2(acc2[i][0], a2, wA.x);
                    fma2(acc2[i][1], a2, wA.y);
                    fma2(acc2[i][2], a2, wB.x);
                    fma2(acc2[i][3], a2, wB.y);
                }
            }
        }
        __syncthreads();
        if (kt + 1 < nk) {
            if (tid < 128) *(float4*)&As[ar][ak] = pa;
#pragma unroll
            for (int it = 0; it < 4; it++) {
                int gidx = tid + it * 256;
                int wr = gidx >> 6, wc = (gidx & 63) * 4;
                *(float4*)&Ws[wr][wc] = pw[it];
            }
        }
        __syncthreads();
    }

    const int c0 = tx * 4, c1 = 128 + tx * 4;
    const float4 gA = *(const float4*)(g + c0);
    const float4 gB = *(const float4*)(g + c1);
    const float4 bA = *(const float4*)(b + c0);
    const float4 bB = *(const float4*)(b + c1);

#pragma unroll
    for (int i = 0; i < 4; i++) {
        const int m = m0 + ty * 4 + i;
        float v[8];
        float2 u0 = unpack2(acc2[i][0]); v[0] = u0.x; v[1] = u0.y;
        float2 u1 = unpack2(acc2[i][1]); v[2] = u1.x; v[3] = u1.y;
        float2 u2 = unpack2(acc2[i][2]); v[4] = u2.x; v[5] = u2.y;
        float2 u3 = unpack2(acc2[i][3]); v[6] = u3.x; v[7] = u3.y;

        float s = 0.f, ss = 0.f;
#pragma unroll
        for (int j = 0; j < 8; j++) { s += v[j]; ss += v[j] * v[j]; }
#pragma unroll
        for (int off = 16; off; off >>= 1) {
            s  += __shfl_xor_sync(0xffffffffu, s, off);
            ss += __shfl_xor_sync(0xffffffffu, ss, off);
        }
        const float mu  = s * (1.f / 256.f);
        const float var = ss * (1.f / 256.f) - mu * mu;
        const float rs  = rsqrtf(var + 1e-5f);

        float r0 = (v[0] - mu) * rs * gA.x + bA.x;
        float r1 = (v[1] - mu) * rs * gA.y + bA.y;
        float r2 = (v[2] - mu) * rs * gA.z + bA.z;
        float r3 = (v[3] - mu) * rs * gA.w + bA.w;
        float r4 = (v[4] - mu) * rs * gB.x + bB.x;
        float r5 = (v[5] - mu) * rs * gB.y + bB.y;
        float r6 = (v[6] - mu) * rs * gB.z + bB.z;
        float r7 = (v[7] - mu) * rs * gB.w + bB.w;

        if (resid) {
            const float* rp = resid + (size_t)m * 256;
            float4 x0 = *(const float4*)(rp + c0);
            float4 x1 = *(const float4*)(rp + c1);
            r0 += x0.x; r1 += x0.y; r2 += x0.z; r3 += x0.w;
            r4 += x1.x; r5 += x1.y; r6 += x1.z; r7 += x1.w;
        }
        float* dst = out + (size_t)m * 256;
        *(float4*)(dst + c0) = make_float4(r0, r1, r2, r3);
        *(float4*)(dst + c1) = make_float4(r4, r5, r6, r7);
    }
}

// ---------------- FlashAttention (fp32, f32x2) — R13 + 2-sync loop --------
// R13 structure; ONLY change: V tile double-buffered, K/V stores moved to
// right after sync A (KsT reads proven done; V store hits the idle buffer).
// One barrier (B) closes the iteration: 2 syncs per key-block instead of 3.
__global__ __launch_bounds__(256) void attn_k(
    const float* __restrict__ Q, const float* __restrict__ Kg,
    const float* __restrict__ Vg, float* __restrict__ O)
{
    extern __shared__ __align__(16) float sm[];
    float* Qs   = sm;                     // [128][68]
    float* KsT  = Qs + 128 * 68;          // [64][128]  (d, s)
    float* Vs   = KsT + 64 * 128;         // [2][128][68]
    float* Ps   = Vs + 2 * 128 * 68;      // [128][128]
    float* sden = Ps + 128 * 128;         // [128]

    const int tid = threadIdx.x;
    const int tx = tid & 15;     // QK cols {tx*4, 64+tx*4}
    const int ty = tid >> 4;     // QK rows ty*8..+7
    const int txv = tid & 7;     // PV cols {txv*4, 32+txv*4}
    const int tyv = tid >> 3;    // PV rows tyv*4..+3
    const int q0 = blockIdx.x * 128;
    const int b = blockIdx.y >> 2;
    const int h = blockIdx.y & 3;

    const float* Qp = Q  + ((size_t)b * 2048 + q0) * 256 + h * 64;
    const float* Kp = Kg + (size_t)b * 2048 * 256 + h * 64;
    const float* Vp = Vg + (size_t)b * 2048 * 256 + h * 64;

    const float QSCALE = 0.18033688011112042f;  // 0.125 * log2(e)

#pragma unroll
    for (int it = 0; it < 8; it++) {
        int g = tid + it * 256;
        int r = g >> 4, c = (g & 15) << 2;
        float4 q = *(const float4*)(Qp + (size_t)r * 256 + c);
        *(float4*)&Qs[r * 68 + c] =
            make_float4(q.x * QSCALE, q.y * QSCALE, q.z * QSCALE, q.w * QSCALE);
    }
#pragma unroll
    for (int it = 0; it < 8; it++) {
        int g = tid + it * 256;
        int s = g & 127, dg = g >> 7;
        float4 kv = *(const float4*)(Kp + (size_t)s * 256 + dg * 4);
        KsT[(dg * 4 + 0) * 128 + s] = kv.x;
        KsT[(dg * 4 + 1) * 128 + s] = kv.y;
        KsT[(dg * 4 + 2) * 128 + s] = kv.z;
        KsT[(dg * 4 + 3) * 128 + s] = kv.w;
    }
#pragma unroll
    for (int it = 0; it < 8; it++) {
        int g = tid + it * 256;
        int s = g >> 4, c = (g & 15) << 2;
        *(float4*)&Vs[s * 68 + c] = *(const float4*)(Vp + (size_t)s * 256 + c);
    }
    __syncthreads();

    ULL o2[4][4];
    float den[8];
#pragma unroll
    for (int i = 0; i < 4; i++)
#pragma unroll
        for (int j = 0; j < 4; j++) o2[i][j] = 0ull;
#pragma unroll
    for (int i = 0; i < 8; i++) den[i] = 0.f;

    for (int kt = 0; kt < 16; kt++) {
        const float* Vcur = Vs + (kt & 1) * 128 * 68;

        // ---- S = Q @ K^T : 8 rows x 8 split cols
        ULL s2[8][4];
#pragma unroll
        for (int i = 0; i < 8; i++)
#pragma unroll
            for (int j = 0; j < 4; j++) s2[i][j] = 0ull;

#pragma unroll
        for (int d4 = 0; d4 < 16; d4++) {
            float4 q4[8];
#pragma unroll
            for (int i = 0; i < 8; i++)
                q4[i] = *(const float4*)&Qs[(ty * 8 + i) * 68 + d4 * 4];
#pragma unroll
            for (int dd = 0; dd < 4; dd++) {
                const float* krow = &KsT[(d4 * 4 + dd) * 128];
                ulonglong2 kA = *(const ulonglong2*)(krow + tx * 4);
                ulonglong2 kB = *(const ulonglong2*)(krow + 64 + tx * 4);
#pragma unroll
                for (int i = 0; i < 8; i++) {
                    ULL qq = bcast2(((const float*)&q4[i])[dd]);
                    fma2(s2[i][0], qq, kA.x);
                    fma2(s2[i][1], qq, kA.y);
                    fma2(s2[i][2], qq, kB.x);
                    fma2(s2[i][3], qq, kB.y);
                }
            }
        }

        // ---- softmax without max-shift: p = 2^S, den += sum(p)
#pragma unroll
        for (int i = 0; i < 8; i++) {
            float p[8];
            float2 t0 = unpack2(s2[i][0]); p[0] = ex2(t0.x); p[1] = ex2(t0.y);
            float2 t1 = unpack2(s2[i][1]); p[2] = ex2(t1.x); p[3] = ex2(t1.y);
            float2 t2 = unpack2(s2[i][2]); p[4] = ex2(t2.x); p[5] = ex2(t2.y);
            float2 t3 = unpack2(s2[i][3]); p[6] = ex2(t3.x); p[7] = ex2(t3.y);
            den[i] += ((p[0] + p[1]) + (p[2] + p[3]))
                    + ((p[4] + p[5]) + (p[6] + p[7]));
            float* pr = &Ps[(ty * 8 + i) * 128];
            *(float4*)(pr + tx * 4)      = make_float4(p[0], p[1], p[2], p[3]);
            *(float4*)(pr + 64 + tx * 4) = make_float4(p[4], p[5], p[6], p[7]);
        }

        // ---- prefetch next K/V into registers
        float4 kpre[8], vpre[8];
        const bool more = (kt + 1 < 16);
        if (more) {
            const float* Kn = Kp + (size_t)(kt + 1) * 128 * 256;
            const float* Vn = Vp + (size_t)(kt + 1) * 128 * 256;
#pragma unroll
            for (int it = 0; it < 8; it++) {
                int g = tid + it * 256;
                int s = g & 127, dg = g >> 7;
                kpre[it] = *(const float4*)(Kn + (size_t)s * 256 + dg * 4);
                int sv = g >> 4, cv = (g & 15) << 2;
                vpre[it] = *(const float4*)(Vn + (size_t)sv * 256 + cv);
            }
        }
        __syncthreads();   // A: Ps visible; all QK reads of KsT done

        // ---- store next K tile (KsT free) and next V tile (idle buffer)
        if (more) {
            float* Vnxt = Vs + ((kt + 1) & 1) * 128 * 68;
#pragma unroll
            for (int it = 0; it < 8; it++) {
                int g = tid + it * 256;
                int s = g & 127, dg = g >> 7;
                float4 kv = kpre[it];
                KsT[(dg * 4 + 0) * 128 + s] = kv.x;
                KsT[(dg * 4 + 1) * 128 + s] = kv.y;
                KsT[(dg * 4 + 2) * 128 + s] = kv.z;
                KsT[(dg * 4 + 3) * 128 + s] = kv.w;
                int sv = g >> 4, cv = (g & 15) << 2;
                *(float4*)&Vnxt[sv * 68 + cv] = vpre[it];
            }
        }

        // ---- O += P @ V : 4 rows x 8 split cols per thread
#pragma unroll
        for (int k4 = 0; k4 < 32; k4++) {
            float4 p4[4];
#pragma unroll
            for (int i = 0; i < 4; i++)
                p4[i] = *(const float4*)&Ps[(tyv * 4 + i) * 128 + k4 * 4];
#pragma unroll
            for (int kk = 0; kk < 4; kk++) {
                const float* vrow = &Vcur[(k4 * 4 + kk) * 68];
                ulonglong2 vA = *(const ulonglong2*)(vrow + txv * 4);
                ulonglong2 vB = *(const ulonglong2*)(vrow + 32 + txv * 4);
#pragma unroll
                for (int i = 0; i < 4; i++) {
                    ULL pp = bcast2(((const float*)&p4[i])[kk]);
                    fma2(o2[i][0], pp, vA.x);
                    fma2(o2[i][1], pp, vA.y);
                    fma2(o2[i][2], pp, vB.x);
                    fma2(o2[i][3], pp, vB.y);
                }
            }
        }
        __syncthreads();   // B: K/V stores visible; Ps reads done
    }

    // ---- denominator: reduce across 16-lane row groups, hand to PV map --
#pragma unroll
    for (int i = 0; i < 8; i++) {
#pragma unroll
        for (int off = 8; off; off >>= 1)
            den[i] += __shfl_xor_sync(0xffffffffu, den[i], off);
    }
    if (tx == 0) {
#pragma unroll
        for (int i = 0; i < 8; i++) sden[ty * 8 + i] = den[i];
    }
    __syncthreads();

    // ---- epilogue (PV map): O / den
    float* Op = O + ((size_t)b * 2048 + q0) * 256 + h * 64;
#pragma unroll
    for (int i = 0; i < 4; i++) {
        const int row = tyv * 4 + i;
        const float inv = 1.f / sden[row];
        float2 a0 = unpack2(o2[i][0]);
        float2 a1 = unpack2(o2[i][1]);
        float2 a2 = unpack2(o2[i][2]);
        float2 a3 = unpack2(o2[i][3]);
        float* dst = Op + (size_t)row * 256;
        *(float4*)(dst + txv * 4) =
            make_float4(a0.x * inv, a0.y * inv, a1.x * inv, a1.y * inv);
        *(float4*)(dst + 32 + txv * 4) =
            make_float4(a2.x * inv, a2.y * inv, a3.x * inv, a3.y * inv);
    }
}

// ---------------- launch -------------------------------------------------
extern "C" void kernel_launch(void* const* d_in, const int* in_sizes, int n_in,
                              void* d_out, int out_size)
{
    (void)in_sizes; (void)n_in; (void)out_size;
    const float* x   = (const float*)d_in[0];
    const float* src = (const float*)d_in[1];
    const float* xpe = (const float*)d_in[2];
    const float* spe = (const float*)d_in[3];
    const float* Wq  = (const float*)d_in[4];
    const float* Wk  = (const float*)d_in[5];
    const float* Wv  = (const float*)d_in[6];
    const float* Wm  = (const float*)d_in[7];
    const float* W1  = (const float*)d_in[8];
    const float* W2  = (const float*)d_in[9];
    const float* g1  = (const float*)d_in[10];
    const float* b1  = (const float*)d_in[11];
    const float* g2  = (const float*)d_in[12];
    const float* b2  = (const float*)d_in[13];
    float* out = (float*)d_out;

    float *Qb, *Kb, *Vb, *Ob, *Msg, *Hb;
    cudaGetSymbolAddress((void**)&Qb,  g_Q);
    cudaGetSymbolAddress((void**)&Kb,  g_K);
    cudaGetSymbolAddress((void**)&Vb,  g_V);
    cudaGetSymbolAddress((void**)&Ob,  g_O);
    cudaGetSymbolAddress((void**)&Msg, g_Msg);
    cudaGetSymbolAddress((void**)&Hb,  g_H);

    // Qs + KsT + 2*Vs + Ps + sden = 203,264 B
    const int ATTN_SMEM = (128 * 68 + 64 * 128 + 2 * 128 * 68 + 128 * 128 + 128) * 4;
    cudaFuncSetAttribute(attn_k, cudaFuncAttributeMaxDynamicSharedMemorySize, ATTN_SMEM);

    const dim3 blk(256);
    // fused Q/K/V projections (rotary on Q,K)
    qkv_k<<<dim3(4, 32, 3), blk>>>(x, src, xpe, spe, Wq, Wk, Wv, Qb, Kb, Vb);
    // attention
    attn_k<<<dim3(16, 8), blk, ATTN_SMEM>>>(Qb, Kb, Vb, Ob);
    // message = LN(O @ Wm)   (fused)
    gemm_ln_k<<<128, blk>>>(Ob, Wm, 256, g1, b1, nullptr, Msg);
    // h = relu(concat(x, message) @ W1)
    gemm_k<true, false><<<dim3(8, 32), blk>>>(x, Msg, 256, W1, nullptr, Hb, 4096, 512, 512);
    // out = x + LN(h @ W2)   (fused)
    gemm_ln_k<<<128, blk>>>(Hb, W2, 512, g2, b2, x, out);
}

// round 17
// speedup vs baseline: 1.0652x; 1.0231x over previous
#include <cuda_runtime.h>
#include <math.h>

typedef unsigned long long ULL;

// ---------------- f32x2 packed-math helpers (sm_100+) --------------------
__device__ __forceinline__ ULL bcast2(float v) {
    ULL r; asm("mov.b64 %0, {%1, %1};" : "=l"(r) : "f"(v)); return r;
}
__device__ __forceinline__ void fma2(ULL& d, ULL a, ULL b) {
    asm("fma.rn.f32x2 %0, %1, %2, %0;" : "+l"(d) : "l"(a), "l"(b));
}
__device__ __forceinline__ float2 unpack2(ULL v) {
    float2 f; asm("mov.b64 {%0, %1}, %2;" : "=f"(f.x), "=f"(f.y) : "l"(v)); return f;
}
__device__ __forceinline__ float ex2(float x) {
    float r; asm("ex2.approx.f32 %0, %1;" : "=f"(r) : "f"(x)); return r;
}

// ---------------- scratch buffers (no allocation allowed) ----------------
__device__ float g_Q[4096 * 256];
__device__ float g_K[4096 * 256];
__device__ float g_V[4096 * 256];
__device__ float g_O[4096 * 256];
__device__ float g_Msg[4096 * 256];

// ---------------- GEMM core (f32x2) — R13 proven version ------------------
template <bool RELU>
__device__ __forceinline__ void gemm_body(
    const float* __restrict__ A0, const float* __restrict__ A1, int kSplit,
    const float* __restrict__ W, const float* __restrict__ pe, bool rotary,
    float* __restrict__ C, int N, int K,
    float (*As)[16], float (*Ws)[64])
{
    const int tid = threadIdx.x;
    const int tx = tid & 15;
    const int ty = tid >> 4;
    const int m0 = blockIdx.y * 128;
    const int n0 = blockIdx.x * 64;

    const int ar = tid >> 2;
    const int ak = (tid & 3) * 4;
    const int wk = tid >> 4;
    const int wc = (tid & 15) * 4;

    ULL acc2[8][2];
#pragma unroll
    for (int i = 0; i < 8; i++) { acc2[i][0] = 0ull; acc2[i][1] = 0ull; }

    const int nk = K >> 4;
    float4 pa0, pa1, pw;

    pa0 = *(const float4*)(A0 + (size_t)(m0 + ar) * kSplit + ak);
    pa1 = *(const float4*)(A0 + (size_t)(m0 + ar + 64) * kSplit + ak);
    pw  = *(const float4*)(W + (size_t)wk * N + n0 + wc);
    *(float4*)&As[ar][ak]      = pa0;
    *(float4*)&As[ar + 64][ak] = pa1;
    *(float4*)&Ws[wk][wc]      = pw;
    __syncthreads();

    for (int kt = 0; kt < nk; kt++) {
        if (kt + 1 < nk) {
            const int kb = (kt + 1) << 4;
            const float* src; int lda, kk;
            if (kb < kSplit) { src = A0; lda = kSplit;     kk = kb; }
            else             { src = A1; lda = K - kSplit; kk = kb - kSplit; }
            pa0 = *(const float4*)(src + (size_t)(m0 + ar) * lda + kk + ak);
            pa1 = *(const float4*)(src + (size_t)(m0 + ar + 64) * lda + kk + ak);
            pw  = *(const float4*)(W + (size_t)(kb + wk) * N + n0 + wc);
        }
#pragma unroll
        for (int k4 = 0; k4 < 4; k4++) {
            float4 av4[8];
#pragma unroll
            for (int i = 0; i < 8; i++)
                av4[i] = *(const float4*)&As[ty * 8 + i][k4 * 4];
#pragma unroll
            for (int kk = 0; kk < 4; kk++) {
                ulonglong2 w2 = *(const ulonglong2*)&Ws[k4 * 4 + kk][tx * 4];
#pragma unroll
                for (int i = 0; i < 8; i++) {
                    ULL a2 = bcast2(((const float*)&av4[i])[kk]);
                    fma2(acc2[i][0], a2, w2.x);
                    fma2(acc2[i][1], a2, w2.y);
                }
            }
        }
        __syncthreads();
        if (kt + 1 < nk) {
            *(float4*)&As[ar][ak]      = pa0;
            *(float4*)&As[ar + 64][ak] = pa1;
            *(float4*)&Ws[wk][wc]      = pw;
        }
        __syncthreads();
    }

#pragma unroll
    for (int i = 0; i < 8; i++) {
        const int m = m0 + ty * 8 + i;
        float2 u0 = unpack2(acc2[i][0]);
        float2 u1 = unpack2(acc2[i][1]);
        float v0 = u0.x, v1 = u0.y, v2 = u1.x, v3 = u1.y;
        if (RELU) {
            v0 = fmaxf(v0, 0.f); v1 = fmaxf(v1, 0.f);
            v2 = fmaxf(v2, 0.f); v3 = fmaxf(v3, 0.f);
        }
        if (rotary) {
            const int c0 = n0 + tx * 4;
            const float* pr = pe + ((size_t)m * 256 + c0) * 2;
            float4 p0 = *(const float4*)pr;
            float4 p1 = *(const float4*)(pr + 4);
            float e = v0, o = v1;
            v0 = e * p0.x - o * p0.y;
            v1 = o * p0.z + e * p0.w;
            e = v2; o = v3;
            v2 = e * p1.x - o * p1.y;
            v3 = o * p1.z + e * p1.w;
        }
        *(float4*)(C + (size_t)m * N + n0 + tx * 4) = make_float4(v0, v1, v2, v3);
    }
}

// Fused Q/K/V projection: z selects {A, W, pe, C, rotary}. 384 CTAs.
__global__ __launch_bounds__(256) void qkv_k(
    const float* __restrict__ x, const float* __restrict__ src,
    const float* __restrict__ xpe, const float* __restrict__ spe,
    const float* __restrict__ Wq, const float* __restrict__ Wk,
    const float* __restrict__ Wv,
    float* __restrict__ Qb, float* __restrict__ Kb, float* __restrict__ Vb)
{
    __shared__ __align__(16) float As[128][16];
    __shared__ __align__(16) float Ws[16][64];
    const int z = blockIdx.z;
    const float* A  = (z == 0) ? x   : src;
    const float* W  = (z == 0) ? Wq  : (z == 1 ? Wk : Wv);
    const float* pe = (z == 0) ? xpe : spe;
    float* C        = (z == 0) ? Qb  : (z == 1 ? Kb : Vb);
    gemm_body<false>(A, nullptr, 256, W, pe, z < 2, C, 256, 256, As, Ws);
}

// ---------------- GEMM + fused LayerNorm (split columns, R13-proven) ------
__global__ __launch_bounds__(256) void gemm_ln_k(
    const float* __restrict__ A, const float* __restrict__ W, int K,
    const float* __restrict__ g, const float* __restrict__ b,
    const float* __restrict__ resid, float* __restrict__ out)
{
    __shared__ __align__(16) float As[32][16];
    __shared__ __align__(16) float Ws[16][256];

    const int tid = threadIdx.x;
    const int tx = tid & 31;
    const int ty = tid >> 5;
    const int m0 = blockIdx.x * 32;

    ULL acc2[4][4];
#pragma unroll
    for (int i = 0; i < 4; i++)
#pragma unroll
        for (int j = 0; j < 4; j++) acc2[i][j] = 0ull;

    const int nk = K >> 4;
    const int ar = tid >> 2, ak = (tid & 3) * 4;

    float4 pa, pw[4];
    if (tid < 128)
        pa = *(const float4*)(A + (size_t)(m0 + ar) * K + ak);
#pragma unroll
    for (int it = 0; it < 4; it++) {
        int gidx = tid + it * 256;
        int wr = gidx >> 6, wc = (gidx & 63) * 4;
        pw[it] = *(const float4*)(W + (size_t)wr * 256 + wc);
    }
    if (tid < 128) *(float4*)&As[ar][ak] = pa;
#pragma unroll
    for (int it = 0; it < 4; it++) {
        int gidx = tid + it * 256;
        int wr = gidx >> 6, wc = (gidx & 63) * 4;
        *(float4*)&Ws[wr][wc] = pw[it];
    }
    __syncthreads();

    for (int kt = 0; kt < nk; kt++) {
        if (kt + 1 < nk) {
            const int kb = (kt + 1) << 4;
            if (tid < 128)
                pa = *(const float4*)(A + (size_t)(m0 + ar) * K + kb + ak);
#pragma unroll
            for (int it = 0; it < 4; it++) {
                int gidx = tid + it * 256;
                int wr = gidx >> 6, wc = (gidx & 63) * 4;
                pw[it] = *(const float4*)(W + (size_t)(kb + wr) * 256 + wc);
            }
        }
#pragma unroll
        for (int k4 = 0; k4 < 4; k4++) {
            float4 av4[4];
#pragma unroll
            for (int i = 0; i < 4; i++)
                av4[i] = *(const float4*)&As[ty * 4 + i][k4 * 4];
#pragma unroll
            for (int kk = 0; kk < 4; kk++) {
                const float* wrow = &Ws[k4 * 4 + kk][0];
                ulonglong2 wA = *(const ulonglong2*)(wrow + tx * 4);
                ulonglong2 wB = *(const ulonglong2*)(wrow + 128 + tx * 4);
#pragma unroll
                for (int i = 0; i < 4; i++) {
                    ULL a2 = bcast2(((const float*)&av4[i])[kk]);
                    fma2(acc2[i][0], a2, wA.x);
                    fma2(acc2[i][1], a2, wA.y);
                    fma2(acc2[i][2], a2, wB.x);
                    fma2(acc2[i][3], a2, wB.y);
                }
            }
        }
        __syncthreads();
        if (kt + 1 < nk) {
            if (tid < 128) *(float4*)&As[ar][ak] = pa;
#pragma unroll
            for (int it = 0; it < 4; it++) {
                int gidx = tid + it * 256;
                int wr = gidx >> 6, wc = (gidx & 63) * 4;
                *(float4*)&Ws[wr][wc] = pw[it];
            }
        }
        __syncthreads();
    }

    const int c0 = tx * 4, c1 = 128 + tx * 4;
    const float4 gA = *(const float4*)(g + c0);
    const float4 gB = *(const float4*)(g + c1);
    const float4 bA = *(const float4*)(b + c0);
    const float4 bB = *(const float4*)(b + c1);

#pragma unroll
    for (int i = 0; i < 4; i++) {
        const int m = m0 + ty * 4 + i;
        float v[8];
        float2 u0 = unpack2(acc2[i][0]); v[0] = u0.x; v[1] = u0.y;
        float2 u1 = unpack2(acc2[i][1]); v[2] = u1.x; v[3] = u1.y;
        float2 u2 = unpack2(acc2[i][2]); v[4] = u2.x; v[5] = u2.y;
        float2 u3 = unpack2(acc2[i][3]); v[6] = u3.x; v[7] = u3.y;

        float s = 0.f, ss = 0.f;
#pragma unroll
        for (int j = 0; j < 8; j++) { s += v[j]; ss += v[j] * v[j]; }
#pragma unroll
        for (int off = 16; off; off >>= 1) {
            s  += __shfl_xor_sync(0xffffffffu, s, off);
            ss += __shfl_xor_sync(0xffffffffu, ss, off);
        }
        const float mu  = s * (1.f / 256.f);
        const float var = ss * (1.f / 256.f) - mu * mu;
        const float rs  = rsqrtf(var + 1e-5f);

        float r0 = (v[0] - mu) * rs * gA.x + bA.x;
        float r1 = (v[1] - mu) * rs * gA.y + bA.y;
        float r2 = (v[2] - mu) * rs * gA.z + bA.z;
        float r3 = (v[3] - mu) * rs * gA.w + bA.w;
        float r4 = (v[4] - mu) * rs * gB.x + bB.x;
        float r5 = (v[5] - mu) * rs * gB.y + bB.y;
        float r6 = (v[6] - mu) * rs * gB.z + bB.z;
        float r7 = (v[7] - mu) * rs * gB.w + bB.w;

        if (resid) {
            const float* rp = resid + (size_t)m * 256;
            float4 x0 = *(const float4*)(rp + c0);
            float4 x1 = *(const float4*)(rp + c1);
            r0 += x0.x; r1 += x0.y; r2 += x0.z; r3 += x0.w;
            r4 += x1.x; r5 += x1.y; r6 += x1.z; r7 += x1.w;
        }
        float* dst = out + (size_t)m * 256;
        *(float4*)(dst + c0) = make_float4(r0, r1, r2, r3);
        *(float4*)(dst + c1) = make_float4(r4, r5, r6, r7);
    }
}

// ---------------- Fused MLP: out = x + LN(relu(concat(x,Msg)@W1) @ W2) ----
// One CTA per 32 rows. Phase 1: h[32][512] computed into smem (4 rows x 16
// cols/thread, mov:fma2 = 1:8, conflict-free W reads). Phase 2: gemm_ln
// structure with A read directly from smem h (warp broadcasts).
__global__ __launch_bounds__(256) void mlp_k(
    const float* __restrict__ x, const float* __restrict__ Msg,
    const float* __restrict__ W1, const float* __restrict__ W2,
    const float* __restrict__ g, const float* __restrict__ b,
    float* __restrict__ out)
{
    extern __shared__ __align__(16) float smf[];
    float* As  = smf;             // [32][16]
    float* Ws1 = As + 512;        // [16][512]
    float* hS  = Ws1 + 8192;      // [32][512]
    float* Ws2 = hS + 16384;      // [16][256]

    const int tid = threadIdx.x;
    const int tx = tid & 31;      // 32 col groups
    const int ty = tid >> 5;      // 8 row groups of 4
    const int m0 = blockIdx.x * 32;
    const int ar = tid >> 2, ak = (tid & 3) * 4;   // A loaders (tid<128)

    // ================= phase 1: h = relu(concat(x,Msg) @ W1) =============
    ULL acc[4][8];
#pragma unroll
    for (int i = 0; i < 4; i++)
#pragma unroll
        for (int j = 0; j < 8; j++) acc[i][j] = 0ull;

    float4 pa; float4 pw[8];
    if (tid < 128)
        pa = *(const float4*)(x + (size_t)(m0 + ar) * 256 + ak);
#pragma unroll
    for (int it = 0; it < 8; it++) {
        int gidx = tid + it * 256;
        int wr = gidx >> 7, wc = (gidx & 127) * 4;
        pw[it] = *(const float4*)(W1 + (size_t)wr * 512 + wc);
    }
    if (tid < 128) *(float4*)&As[ar * 16 + ak] = pa;
#pragma unroll
    for (int it = 0; it < 8; it++) {
        int gidx = tid + it * 256;
        int wr = gidx >> 7, wc = (gidx & 127) * 4;
        *(float4*)&Ws1[wr * 512 + wc] = pw[it];
    }
    __syncthreads();

    for (int kt = 0; kt < 32; kt++) {
        const bool more = (kt + 1 < 32);
        if (more) {
            const int kb = (kt + 1) << 4;
            if (tid < 128) {
                const float* src = (kb < 256) ? x : Msg;
                const int kk0 = (kb < 256) ? kb : kb - 256;
                pa = *(const float4*)(src + (size_t)(m0 + ar) * 256 + kk0 + ak);
            }
#pragma unroll
            for (int it = 0; it < 8; it++) {
                int gidx = tid + it * 256;
                int wr = gidx >> 7, wc = (gidx & 127) * 4;
                pw[it] = *(const float4*)(W1 + (size_t)(kb + wr) * 512 + wc);
            }
        }
#pragma unroll
        for (int k4 = 0; k4 < 4; k4++) {
            float4 av4[4];
#pragma unroll
            for (int i = 0; i < 4; i++)
                av4[i] = *(const float4*)&As[(ty * 4 + i) * 16 + k4 * 4];
#pragma unroll
            for (int kk = 0; kk < 4; kk++) {
                const float* wrow = &Ws1[(k4 * 4 + kk) * 512];
                ulonglong2 w0 = *(const ulonglong2*)(wrow + tx * 4);
                ulonglong2 w1 = *(const ulonglong2*)(wrow + 128 + tx * 4);
                ulonglong2 w2 = *(const ulonglong2*)(wrow + 256 + tx * 4);
                ulonglong2 w3 = *(const ulonglong2*)(wrow + 384 + tx * 4);
#pragma unroll
                for (int i = 0; i < 4; i++) {
                    ULL a2 = bcast2(((const float*)&av4[i])[kk]);
                    fma2(acc[i][0], a2, w0.x);
                    fma2(acc[i][1], a2, w0.y);
                    fma2(acc[i][2], a2, w1.x);
                    fma2(acc[i][3], a2, w1.y);
                    fma2(acc[i][4], a2, w2.x);
                    fma2(acc[i][5], a2, w2.y);
                    fma2(acc[i][6], a2, w3.x);
                    fma2(acc[i][7], a2, w3.y);
                }
            }
        }
        __syncthreads();
        if (more) {
            if (tid < 128) *(float4*)&As[ar * 16 + ak] = pa;
#pragma unroll
            for (int it = 0; it < 8; it++) {
                int gidx = tid + it * 256;
                int wr = gidx >> 7, wc = (gidx & 127) * 4;
                *(float4*)&Ws1[wr * 512 + wc] = pw[it];
            }
        }
        __syncthreads();
    }

    // relu + store h to smem
#pragma unroll
    for (int i = 0; i < 4; i++) {
        const int row = ty * 4 + i;
#pragma unroll
        for (int gj = 0; gj < 4; gj++) {
            float2 u0 = unpack2(acc[i][gj * 2]);
            float2 u1 = unpack2(acc[i][gj * 2 + 1]);
            *(float4*)&hS[row * 512 + gj * 128 + tx * 4] = make_float4(
                fmaxf(u0.x, 0.f), fmaxf(u0.y, 0.f),
                fmaxf(u1.x, 0.f), fmaxf(u1.y, 0.f));
        }
    }
    __syncthreads();

    // ================= phase 2: out = x + LN(h @ W2) ======================
    ULL acc2[4][4];
#pragma unroll
    for (int i = 0; i < 4; i++)
#pragma unroll
        for (int j = 0; j < 4; j++) acc2[i][j] = 0ull;

    float4 pw2[4];
#pragma unroll
    for (int it = 0; it < 4; it++) {
        int gidx = tid + it * 256;
        int wr = gidx >> 6, wc = (gidx & 63) * 4;
        pw2[it] = *(const float4*)(W2 + (size_t)wr * 256 + wc);
    }
#pragma unroll
    for (int it = 0; it < 4; it++) {
        int gidx = tid + it * 256;
        int wr = gidx >> 6, wc = (gidx & 63) * 4;
        *(float4*)&Ws2[wr * 256 + wc] = pw2[it];
    }
    __syncthreads();

    for (int kt = 0; kt < 32; kt++) {
        const bool more = (kt + 1 < 32);
        if (more) {
            const int kb = (kt + 1) << 4;
#pragma unroll
            for (int it = 0; it < 4; it++) {
                int gidx = tid + it * 256;
                int wr = gidx >> 6, wc = (gidx & 63) * 4;
                pw2[it] = *(const float4*)(W2 + (size_t)(kb + wr) * 256 + wc);
            }
        }
#pragma unroll
        for (int k4 = 0; k4 < 4; k4++) {
            float4 av4[4];
#pragma unroll
            for (int i = 0; i < 4; i++)
                av4[i] = *(const float4*)&hS[(ty * 4 + i) * 512 + kt * 16 + k4 * 4];
#pragma unroll
            for (int kk = 0; kk < 4; kk++) {
                const float* wrow = &Ws2[(k4 * 4 + kk) * 256];
                ulonglong2 wA = *(const ulonglong2*)(wrow + tx * 4);
                ulonglong2 wB = *(const ulonglong2*)(wrow + 128 + tx * 4);
#pragma unroll
                for (int i = 0; i < 4; i++) {
                    ULL a2 = bcast2(((const float*)&av4[i])[kk]);
                    fma2(acc2[i][0], a2, wA.x);
                    fma2(acc2[i][1], a2, wA.y);
                    fma2(acc2[i][2], a2, wB.x);
                    fma2(acc2[i][3], a2, wB.y);
                }
            }
        }
        __syncthreads();
        if (more) {
#pragma unroll
            for (int it = 0; it < 4; it++) {
                int gidx = tid + it * 256;
                int wr = gidx >> 6, wc = (gidx & 63) * 4;
                *(float4*)&Ws2[wr * 256 + wc] = pw2[it];
            }
        }
        __syncthreads();
    }

    // LN + residual epilogue
    const int c0 = tx * 4, c1 = 128 + tx * 4;
    const float4 gA = *(const float4*)(g + c0);
    const float4 gB = *(const float4*)(g + c1);
    const float4 bA = *(const float4*)(b + c0);
    const float4 bB = *(const float4*)(b + c1);

#pragma unroll
    for (int i = 0; i < 4; i++) {
        const int m = m0 + ty * 4 + i;
        float v[8];
        float2 u0 = unpack2(acc2[i][0]); v[0] = u0.x; v[1] = u0.y;
        float2 u1 = unpack2(acc2[i][1]); v[2] = u1.x; v[3] = u1.y;
        float2 u2 = unpack2(acc2[i][2]); v[4] = u2.x; v[5] = u2.y;
        float2 u3 = unpack2(acc2[i][3]); v[6] = u3.x; v[7] = u3.y;

        float s = 0.f, ss = 0.f;
#pragma unroll
        for (int j = 0; j < 8; j++) { s += v[j]; ss += v[j] * v[j]; }
#pragma unroll
        for (int off = 16; off; off >>= 1) {
            s  += __shfl_xor_sync(0xffffffffu, s, off);
            ss += __shfl_xor_sync(0xffffffffu, ss, off);
        }
        const float mu  = s * (1.f / 256.f);
        const float var = ss * (1.f / 256.f) - mu * mu;
        const float rs  = rsqrtf(var + 1e-5f);

        float r0 = (v[0] - mu) * rs * gA.x + bA.x;
        float r1 = (v[1] - mu) * rs * gA.y + bA.y;
        float r2 = (v[2] - mu) * rs * gA.z + bA.z;
        float r3 = (v[3] - mu) * rs * gA.w + bA.w;
        float r4 = (v[4] - mu) * rs * gB.x + bB.x;
        float r5 = (v[5] - mu) * rs * gB.y + bB.y;
        float r6 = (v[6] - mu) * rs * gB.z + bB.z;
        float r7 = (v[7] - mu) * rs * gB.w + bB.w;

        const float* rp = x + (size_t)m * 256;
        float4 x0 = *(const float4*)(rp + c0);
        float4 x1 = *(const float4*)(rp + c1);
        r0 += x0.x; r1 += x0.y; r2 += x0.z; r3 += x0.w;
        r4 += x1.x; r5 += x1.y; r6 += x1.z; r7 += x1.w;

        float* dst = out + (size_t)m * 256;
        *(float4*)(dst + c0) = make_float4(r0, r1, r2, r3);
        *(float4*)(dst + c1) = make_float4(r4, r5, r6, r7);
    }
}

// ---------------- FlashAttention (fp32, f32x2) — R13 proven version ------
__global__ __launch_bounds__(256) void attn_k(
    const float* __restrict__ Q, const float* __restrict__ Kg,
    const float* __restrict__ Vg, float* __restrict__ O)
{
    extern __shared__ __align__(16) float sm[];
    float* Qs   = sm;                     // [128][68]
    float* Vs   = Qs + 128 * 68;          // [128][68]
    float* KsT  = Vs + 128 * 68;          // [64][128]  (d, s)
    float* Ps   = KsT + 64 * 128;         // [128][128]
    float* sden = Ps + 128 * 128;         // [128]

    const int tid = threadIdx.x;
    const int tx = tid & 15;     // QK cols {tx*4, 64+tx*4}
    const int ty = tid >> 4;     // QK rows ty*8..+7
    const int txv = tid & 7;     // PV cols {txv*4, 32+txv*4}
    const int tyv = tid >> 3;    // PV rows tyv*4..+3
    const int q0 = blockIdx.x * 128;
    const int b = blockIdx.y >> 2;
    const int h = blockIdx.y & 3;

    const float* Qp = Q  + ((size_t)b * 2048 + q0) * 256 + h * 64;
    const float* Kp = Kg + (size_t)b * 2048 * 256 + h * 64;
    const float* Vp = Vg + (size_t)b * 2048 * 256 + h * 64;

    const float QSCALE = 0.18033688011112042f;  // 0.125 * log2(e)

#pragma unroll
    for (int it = 0; it < 8; it++) {
        int g = tid + it * 256;
        int r = g >> 4, c = (g & 15) << 2;
        float4 q = *(const float4*)(Qp + (size_t)r * 256 + c);
        *(float4*)&Qs[r * 68 + c] =
            make_float4(q.x * QSCALE, q.y * QSCALE, q.z * QSCALE, q.w * QSCALE);
    }
#pragma unroll
    for (int it = 0; it < 8; it++) {
        int g = tid + it * 256;
        int s = g & 127, dg = g >> 7;
        float4 kv = *(const float4*)(Kp + (size_t)s * 256 + dg * 4);
        KsT[(dg * 4 + 0) * 128 + s] = kv.x;
        KsT[(dg * 4 + 1) * 128 + s] = kv.y;
        KsT[(dg * 4 + 2) * 128 + s] = kv.z;
        KsT[(dg * 4 + 3) * 128 + s] = kv.w;
    }
#pragma unroll
    for (int it = 0; it < 8; it++) {
        int g = tid + it * 256;
        int s = g >> 4, c = (g & 15) << 2;
        *(float4*)&Vs[s * 68 + c] = *(const float4*)(Vp + (size_t)s * 256 + c);
    }
    __syncthreads();

    ULL o2[4][4];
    float den[8];
#pragma unroll
    for (int i = 0; i < 4; i++)
#pragma unroll
        for (int j = 0; j < 4; j++) o2[i][j] = 0ull;
#pragma unroll
    for (int i = 0; i < 8; i++) den[i] = 0.f;

    for (int kt = 0; kt < 16; kt++) {
        ULL s2[8][4];
#pragma unroll
        for (int i = 0; i < 8; i++)
#pragma unroll
            for (int j = 0; j < 4; j++) s2[i][j] = 0ull;

#pragma unroll
        for (int d4 = 0; d4 < 16; d4++) {
            float4 q4[8];
#pragma unroll
            for (int i = 0; i < 8; i++)
                q4[i] = *(const float4*)&Qs[(ty * 8 + i) * 68 + d4 * 4];
#pragma unroll
            for (int dd = 0; dd < 4; dd++) {
                const float* krow = &KsT[(d4 * 4 + dd) * 128];
                ulonglong2 kA = *(const ulonglong2*)(krow + tx * 4);
                ulonglong2 kB = *(const ulonglong2*)(krow + 64 + tx * 4);
#pragma unroll
                for (int i = 0; i < 8; i++) {
                    ULL qq = bcast2(((const float*)&q4[i])[dd]);
                    fma2(s2[i][0], qq, kA.x);
                    fma2(s2[i][1], qq, kA.y);
                    fma2(s2[i][2], qq, kB.x);
                    fma2(s2[i][3], qq, kB.y);
                }
            }
        }

#pragma unroll
        for (int i = 0; i < 8; i++) {
            float p[8];
            float2 t0 = unpack2(s2[i][0]); p[0] = ex2(t0.x); p[1] = ex2(t0.y);
            float2 t1 = unpack2(s2[i][1]); p[2] = ex2(t1.x); p[3] = ex2(t1.y);
            float2 t2 = unpack2(s2[i][2]); p[4] = ex2(t2.x); p[5] = ex2(t2.y);
            float2 t3 = unpack2(s2[i][3]); p[6] = ex2(t3.x); p[7] = ex2(t3.y);
            den[i] += ((p[0] + p[1]) + (p[2] + p[3]))
                    + ((p[4] + p[5]) + (p[6] + p[7]));
            float* pr = &Ps[(ty * 8 + i) * 128];
            *(float4*)(pr + tx * 4)      = make_float4(p[0], p[1], p[2], p[3]);
            *(float4*)(pr + 64 + tx * 4) = make_float4(p[4], p[5], p[6], p[7]);
        }

        float4 kpre[8], vpre[8];
        const bool more = (kt + 1 < 16);
        if (more) {
            const float* Kn = Kp + (size_t)(kt + 1) * 128 * 256;
            const float* Vn = Vp + (size_t)(kt + 1) * 128 * 256;
#pragma unroll
            for (int it = 0; it < 8; it++) {
                int g = tid + it * 256;
                int s = g & 127, dg = g >> 7;
                kpre[it] = *(const float4*)(Kn + (size_t)s * 256 + dg * 4);
                int sv = g >> 4, cv = (g & 15) << 2;
                vpre[it] = *(const float4*)(Vn + (size_t)sv * 256 + cv);
            }
        }
        __syncthreads();   // A

#pragma unroll
        for (int k4 = 0; k4 < 32; k4++) {
            float4 p4[4];
#pragma unroll
            for (int i = 0; i < 4; i++)
                p4[i] = *(const float4*)&Ps[(tyv * 4 + i) * 128 + k4 * 4];
#pragma unroll
            for (int kk = 0; kk < 4; kk++) {
                const float* vrow = &Vs[(k4 * 4 + kk) * 68];
                ulonglong2 vA = *(const ulonglong2*)(vrow + txv * 4);
                ulonglong2 vB = *(const ulonglong2*)(vrow + 32 + txv * 4);
#pragma unroll
                for (int i = 0; i < 4; i++) {
                    ULL pp = bcast2(((const float*)&p4[i])[kk]);
                    fma2(o2[i][0], pp, vA.x);
                    fma2(o2[i][1], pp, vA.y);
                    fma2(o2[i][2], pp, vB.x);
                    fma2(o2[i][3], pp, vB.y);
                }
            }
        }
        __syncthreads();   // B

        if (more) {
#pragma unroll
            for (int it = 0; it < 8; it++) {
                int g = tid + it * 256;
                int s = g & 127, dg = g >> 7;
                float4 kv = kpre[it];
                KsT[(dg * 4 + 0) * 128 + s] = kv.x;
                KsT[(dg * 4 + 1) * 128 + s] = kv.y;
                KsT[(dg * 4 + 2) * 128 + s] = kv.z;
                KsT[(dg * 4 + 3) * 128 + s] = kv.w;
                int sv = g >> 4, cv = (g & 15) << 2;
                *(float4*)&Vs[sv * 68 + cv] = vpre[it];
            }
        }
        __syncthreads();   // C
    }

#pragma unroll
    for (int i = 0; i < 8; i++) {
#pragma unroll
        for (int off = 8; off; off >>= 1)
            den[i] += __shfl_xor_sync(0xffffffffu, den[i], off);
    }
    if (tx == 0) {
#pragma unroll
        for (int i = 0; i < 8; i++) sden[ty * 8 + i] = den[i];
    }
    __syncthreads();

    float* Op = O + ((size_t)b * 2048 + q0) * 256 + h * 64;
#pragma unroll
    for (int i = 0; i < 4; i++) {
        const int row = tyv * 4 + i;
        const float inv = 1.f / sden[row];
        float2 a0 = unpack2(o2[i][0]);
        float2 a1 = unpack2(o2[i][1]);
        float2 a2 = unpack2(o2[i][2]);
        float2 a3 = unpack2(o2[i][3]);
        float* dst = Op + (size_t)row * 256;
        *(float4*)(dst + txv * 4) =
            make_float4(a0.x * inv, a0.y * inv, a1.x * inv, a1.y * inv);
        *(float4*)(dst + 32 + txv * 4) =
            make_float4(a2.x * inv, a2.y * inv, a3.x * inv, a3.y * inv);
    }
}

// ---------------- launch -------------------------------------------------
extern "C" void kernel_launch(void* const* d_in, const int* in_sizes, int n_in,
                              void* d_out, int out_size)
{
    (void)in_sizes; (void)n_in; (void)out_size;
    const float* x   = (const float*)d_in[0];
    const float* src = (const float*)d_in[1];
    const float* xpe = (const float*)d_in[2];
    const float* spe = (const float*)d_in[3];
    const float* Wq  = (const float*)d_in[4];
    const float* Wk  = (const float*)d_in[5];
    const float* Wv  = (const float*)d_in[6];
    const float* Wm  = (const float*)d_in[7];
    const float* W1  = (const float*)d_in[8];
    const float* W2  = (const float*)d_in[9];
    const float* g1  = (const float*)d_in[10];
    const float* b1  = (const float*)d_in[11];
    const float* g2  = (const float*)d_in[12];
    const float* b2  = (const float*)d_in[13];
    float* out = (float*)d_out;

    float *Qb, *Kb, *Vb, *Ob, *Msg;
    cudaGetSymbolAddress((void**)&Qb,  g_Q);
    cudaGetSymbolAddress((void**)&Kb,  g_K);
    cudaGetSymbolAddress((void**)&Vb,  g_V);
    cudaGetSymbolAddress((void**)&Ob,  g_O);
    cudaGetSymbolAddress((void**)&Msg, g_Msg);

    const int ATTN_SMEM = (128 * 68 + 128 * 68 + 64 * 128 + 128 * 128 + 128) * 4;
    cudaFuncSetAttribute(attn_k, cudaFuncAttributeMaxDynamicSharedMemorySize, ATTN_SMEM);
    const int MLP_SMEM = (512 + 8192 + 16384 + 4096) * 4;   // 116,736 B
    cudaFuncSetAttribute(mlp_k, cudaFuncAttributeMaxDynamicSharedMemorySize, MLP_SMEM);

    const dim3 blk(256);
    // fused Q/K/V projections (rotary on Q,K)
    qkv_k<<<dim3(4, 32, 3), blk>>>(x, src, xpe, spe, Wq, Wk, Wv, Qb, Kb, Vb);
    // attention
    attn_k<<<dim3(16, 8), blk, ATTN_SMEM>>>(Qb, Kb, Vb, Ob);
    // message = LN(O @ Wm)
    gemm_ln_k<<<128, blk>>>(Ob, Wm, 256, g1, b1, nullptr, Msg);
    // out = x + LN(relu(concat(x,Msg)@W1) @ W2)   (fully fused MLP)
    mlp_k<<<128, blk, MLP_SMEM>>>(x, Msg, W1, W2, g2, b2, out);
}